// round 1
// baseline (speedup 1.0000x reference)
#include <cuda_runtime.h>
#include <math.h>

// Problem shape (fixed by setup_inputs)
#define Bb   32
#define Hh   64
#define Ww   48
#define Cc   256
#define Dd   32
#define BG   256            // Bb * groups(8)
#define NPIX (Hh*Ww)        // 3072
#define LN_EPS 1e-3f
#define NCHUNK 6            // pass3 blocks per bg

// Scratch (device globals — no allocation allowed)
__device__ float g_rowmean[BG*Hh*Dd];
__device__ float g_colmean[BG*Ww*Dd];
__device__ float g_xh[BG*Hh*Dd];
__device__ float g_xw[BG*Ww*Dd];
__device__ float g_Apart[BG*NCHUNK*Dd];
__device__ float g_Bpart[BG*NCHUNK];
__device__ float g_c[BG*Dd];       // x21 * gamma
__device__ float g_csum[BG];       // sum(x21*gamma)
__device__ float g_cb[BG];         // dot(x21, beta)
__device__ float g_weff[BG*9*Dd];  // x11-projected conv3x3 kernel
__device__ float g_beff[BG];       // dot(x11, conv3x3_b)

__device__ __forceinline__ float wsum(float v){
#pragma unroll
    for (int o = 16; o; o >>= 1) v += __shfl_xor_sync(0xffffffffu, v, o);
    return v;
}
__device__ __forceinline__ float wmax(float v){
#pragma unroll
    for (int o = 16; o; o >>= 1) v = fmaxf(v, __shfl_xor_sync(0xffffffffu, v, o));
    return v;
}

// ---------------------------------------------------------------------------
// Pass 1: per-(bg) row means [H,d] and col means [W,d]. One block per bg.
// ---------------------------------------------------------------------------
__global__ void pass1(const float* __restrict__ x)
{
    int bg = blockIdx.x;
    int b = bg >> 3, gi = bg & 7;
    int lane = threadIdx.x & 31, warp = threadIdx.x >> 5;   // 16 warps
    const float* xb = x + ((size_t)b*Hh)*Ww*Cc + gi*Dd + lane;

    // row means: warp handles rows warp, warp+16, ...
    for (int h = warp; h < Hh; h += 16) {
        float s = 0.f;
        const float* rp = xb + (size_t)h*Ww*Cc;
        for (int w = 0; w < Ww; ++w) s += rp[(size_t)w*Cc];
        g_rowmean[(bg*Hh + h)*Dd + lane] = s * (1.0f/Ww);
    }
    // col means
    for (int w = warp; w < Ww; w += 16) {
        float s = 0.f;
        const float* cp = xb + (size_t)w*Cc;
        for (int h = 0; h < Hh; ++h) s += cp[(size_t)h*Ww*Cc];
        g_colmean[(bg*Ww + w)*Dd + lane] = s * (1.0f/Hh);
    }
}

// ---------------------------------------------------------------------------
// Pass 2: conv1x1+sigmoid gates (xh, xw); analytic mean(x2) -> softmax -> x21,
// plus c = x21*gamma, csum, cb. One block (128 thr) per bg.
// ---------------------------------------------------------------------------
__global__ void pass2(const float* __restrict__ x,
                      const float* __restrict__ w1x1,
                      const float* __restrict__ b1,
                      const float* __restrict__ w3,
                      const float* __restrict__ b3,
                      const float* __restrict__ gamma,
                      const float* __restrict__ beta)
{
    __shared__ float smW[Dd*Dd];
    __shared__ float smS[9*Dd];
    int bg = blockIdx.x;
    int b = bg >> 3, gi = bg & 7;
    int tid = threadIdx.x;
    int lane = tid & 31, warp = tid >> 5;   // 4 warps

    for (int i = tid; i < Dd*Dd; i += blockDim.x) smW[i] = w1x1[i];
    __syncthreads();

    float bias = b1[lane];
    for (int p = warp; p < Hh + Ww; p += 4) {
        float v = (p < Hh) ? g_rowmean[(bg*Hh + p)*Dd + lane]
                           : g_colmean[(bg*Ww + (p - Hh))*Dd + lane];
        float acc = bias;
#pragma unroll
        for (int i = 0; i < Dd; ++i) {
            float vi = __shfl_sync(0xffffffffu, v, i);
            acc += vi * smW[i*Dd + lane];
        }
        float s = 1.f/(1.f + expf(-acc));
        if (p < Hh) g_xh[(bg*Hh + p)*Dd + lane] = s;
        else        g_xw[(bg*Ww + (p - Hh))*Dd + lane] = s;
    }

    if (warp == 0) {
        int i = lane;
        // region sums for SAME 3x3 conv mean
        float T = 0.f;
        for (int h = 0; h < Hh; ++h) T += g_rowmean[(bg*Hh + h)*Dd + i];
        T *= (float)Ww;
        float R0 = g_rowmean[(bg*Hh + 0     )*Dd + i] * (float)Ww;
        float RL = g_rowmean[(bg*Hh + Hh - 1)*Dd + i] * (float)Ww;
        float C0 = g_colmean[(bg*Ww + 0     )*Dd + i] * (float)Hh;
        float CL = g_colmean[(bg*Ww + Ww - 1)*Dd + i] * (float)Hh;
        const float* xb = x + ((size_t)b*Hh)*Ww*Cc + gi*Dd + i;
        float ctl = xb[0];
        float ctr = xb[(size_t)(Ww-1)*Cc];
        float cbl = xb[((size_t)(Hh-1)*Ww)*Cc];
        float cbr = xb[((size_t)(Hh-1)*Ww + (Ww-1))*Cc];
#pragma unroll
        for (int dy = -1; dy <= 1; ++dy) {
#pragma unroll
            for (int dx = -1; dx <= 1; ++dx) {
                float eR = (dy == -1) ? RL : (dy == 1) ? R0 : 0.f;
                float eC = (dx == -1) ? CL : (dx == 1) ? C0 : 0.f;
                float corner = 0.f;
                if (dy == -1 && dx == -1) corner = cbr;
                if (dy == -1 && dx ==  1) corner = cbl;
                if (dy ==  1 && dx == -1) corner = ctr;
                if (dy ==  1 && dx ==  1) corner = ctl;
                smS[((dy+1)*3 + (dx+1))*Dd + i] = T - eR - eC + corner;
            }
        }
        __syncwarp();
        int e = lane;
        float acc = 0.f;
        for (int k = 0; k < 9; ++k) {
#pragma unroll
            for (int ii = 0; ii < Dd; ++ii)
                acc += w3[(k*Dd + ii)*Dd + e] * smS[k*Dd + ii];
        }
        float m2 = acc * (1.f/NPIX) + b3[e];
        float mx = wmax(m2);
        float pz = expf(m2 - mx);
        float ps = wsum(pz);
        float x21 = pz/ps;
        float cv = x21 * gamma[e];
        g_c[bg*Dd + e] = cv;
        float cs  = wsum(cv);
        float cbv = wsum(x21 * beta[e]);
        if (e == 0) { g_csum[bg] = cs; g_cb[bg] = cbv; }
    }
}

// ---------------------------------------------------------------------------
// Pass 3: streaming LN-stat reduction: A_e = sum rs*y_e, Bs = sum rs*mu.
// grid = BG*NCHUNK blocks, 512 threads (16 warps), warp = one pixel / step.
// ---------------------------------------------------------------------------
__global__ void pass3(const float* __restrict__ x)
{
    __shared__ float sA[16*Dd];
    __shared__ float sB[16];
    int bg = blockIdx.x / NCHUNK, chunk = blockIdx.x % NCHUNK;
    int b = bg >> 3, gi = bg & 7;
    int lane = threadIdx.x & 31, warp = threadIdx.x >> 5;
    const float* xb = x + ((size_t)b*Hh)*Ww*Cc + gi*Dd + lane;

    float accA = 0.f, accB = 0.f;
    int pix0 = chunk * 512;
#pragma unroll 4
    for (int j = 0; j < 32; ++j) {
        int p = pix0 + j*16 + warp;
        int h = p / Ww, w = p - h*Ww;
        float gx = xb[((size_t)h*Ww + w)*Cc];
        float y = gx * g_xh[(bg*Hh + h)*Dd + lane] * g_xw[(bg*Ww + w)*Dd + lane];
        float mu = wsum(y) * (1.f/Dd);
        float t = y - mu;
        float var = wsum(t*t) * (1.f/Dd);
        float rs = rsqrtf(var + LN_EPS);
        accA += rs * y;
        accB += rs * mu;
    }
    sA[warp*Dd + lane] = accA;
    if (lane == 0) sB[warp] = accB;
    __syncthreads();
    if (warp == 0) {
        float s = 0.f;
        for (int k = 0; k < 16; ++k) s += sA[k*Dd + lane];
        g_Apart[(bg*NCHUNK + chunk)*Dd + lane] = s;
        if (lane == 0) {
            float sb = 0.f;
            for (int k = 0; k < 16; ++k) sb += sB[k];
            g_Bpart[bg*NCHUNK + chunk] = sb;
        }
    }
}

// ---------------------------------------------------------------------------
// Pass 4: x11 = softmax(GAP(x1)); weff[k,i] = sum_e w3[k,i,e]*x11[e]; beff.
// One block (288 thr) per bg.
// ---------------------------------------------------------------------------
__global__ void pass4(const float* __restrict__ w3,
                      const float* __restrict__ b3,
                      const float* __restrict__ gamma,
                      const float* __restrict__ beta)
{
    __shared__ float x11sm[Dd];
    int bg = blockIdx.x;
    int tid = threadIdx.x;
    if (tid < 32) {
        int e = tid;
        float A = 0.f, Bs = 0.f;
        for (int c = 0; c < NCHUNK; ++c) {
            A  += g_Apart[(bg*NCHUNK + c)*Dd + e];
            Bs += g_Bpart[bg*NCHUNK + c];
        }
        float v = gamma[e] * (A - Bs) * (1.f/NPIX) + beta[e];
        float mx = wmax(v);
        float p = expf(v - mx);
        float ps = wsum(p);
        float x11 = p/ps;
        x11sm[e] = x11;
        float be = wsum(x11 * b3[e]);
        if (e == 0) g_beff[bg] = be;
    }
    __syncthreads();
    if (tid < 288) {
        int k = tid >> 5, i = tid & 31;
        float acc = 0.f;
#pragma unroll
        for (int e = 0; e < Dd; ++e) acc += w3[(k*Dd + i)*Dd + e] * x11sm[e];
        g_weff[(bg*9 + k)*Dd + i] = acc;
    }
}

// ---------------------------------------------------------------------------
// Pass 5: per pixel: w1 (projected 3x3 conv), recompute LN -> w2, gate, out.
// grid = BG*Hh (one block per pixel-row), 256 thr = 8 warps, warp = pixel.
// ---------------------------------------------------------------------------
__global__ void pass5(const float* __restrict__ x, float* __restrict__ out)
{
    int bg = blockIdx.x / Hh, h = blockIdx.x % Hh;
    int b = bg >> 3, gi = bg & 7;
    int lane = threadIdx.x & 31, warp = threadIdx.x >> 5;
    const float* xb = x + ((size_t)b*Hh)*Ww*Cc + gi*Dd + lane;
    float* ob = out + ((size_t)b*Hh)*Ww*Cc + gi*Dd + lane;

    float xhv  = g_xh[(bg*Hh + h)*Dd + lane];
    float cv   = g_c[bg*Dd + lane];
    float csum = g_csum[bg], cb = g_cb[bg], beff = g_beff[bg];
    float wk[9];
#pragma unroll
    for (int k = 0; k < 9; ++k) wk[k] = g_weff[(bg*9 + k)*Dd + lane];

    for (int w = warp; w < Ww; w += 8) {
        float conv = 0.f, gxc = 0.f;
#pragma unroll
        for (int dy = -1; dy <= 1; ++dy) {
            int hh = h + dy;
            if (hh < 0 || hh >= Hh) continue;
            const float* rp = xb + (size_t)hh*Ww*Cc;
#pragma unroll
            for (int dx = -1; dx <= 1; ++dx) {
                int ww = w + dx;
                if (ww < 0 || ww >= Ww) continue;
                float v = rp[(size_t)ww*Cc];
                conv += v * wk[(dy+1)*3 + (dx+1)];
                if (dy == 0 && dx == 0) gxc = v;
            }
        }
        float w1 = wsum(conv) + beff;
        float y  = gxc * xhv * g_xw[(bg*Ww + w)*Dd + lane];
        float mu = wsum(y) * (1.f/Dd);
        float t  = y - mu;
        float var = wsum(t*t) * (1.f/Dd);
        float rs  = rsqrtf(var + LN_EPS);
        float dotcy = wsum(cv * y);
        float w2 = rs * (dotcy - mu*csum) + cb;
        float gate = 1.f/(1.f + expf(-(w1 + w2)));
        ob[((size_t)h*Ww + w)*Cc] = gxc * gate;
    }
}

// ---------------------------------------------------------------------------
extern "C" void kernel_launch(void* const* d_in, const int* in_sizes, int n_in,
                              void* d_out, int out_size)
{
    const float* x   = (const float*)d_in[0];
    const float* w1  = (const float*)d_in[1];
    const float* b1  = (const float*)d_in[2];
    const float* w3  = (const float*)d_in[3];
    const float* b3  = (const float*)d_in[4];
    const float* gm  = (const float*)d_in[5];
    const float* bt  = (const float*)d_in[6];
    float* out = (float*)d_out;

    pass1<<<BG, 512>>>(x);
    pass2<<<BG, 128>>>(x, w1, b1, w3, b3, gm, bt);
    pass3<<<BG*NCHUNK, 512>>>(x);
    pass4<<<BG, 288>>>(w3, b3, gm, bt);
    pass5<<<BG*Hh, 256>>>(x, out);
}